// round 1
// baseline (speedup 1.0000x reference)
#include <cuda_runtime.h>
#include <cstdint>
#include <cstddef>

// Problem dims
constexpr int kB  = 128;   // batch
constexpr int kT  = 256;   // timesteps
constexpr int kI  = 256;   // input features
constexpr int kH  = 512;   // hidden
constexpr int kO  = 128;   // output
constexpr int kFH = 4 * kH;           // 2048 (gate rows i,f,g,o)
constexpr int kBH = kB * kH;          // 65536
constexpr int kBT = kB * kT;          // 32768

// Scratch (device-global; no dynamic allocation allowed)
__device__ float g_xp0[(size_t)kBT * kFH];  // layer-0 input projection (+biases), 256 MB
__device__ float g_h1[2][kBH];              // layer-1 hidden, double buffered
__device__ float g_h2[2][kBH];              // layer-2 hidden, double buffered
__device__ float g_c1[kBH];                 // layer-1 cell state
__device__ float g_c2[kBH];                 // layer-2 cell state

enum { MODE_PROJ0 = 0, MODE_STEP0 = 1, MODE_STEP1 = 2, MODE_FC = 3 };

__device__ __forceinline__ float to_tf32(float x) {
    uint32_t u;
    asm("cvt.rna.tf32.f32 %0, %1;" : "=r"(u) : "f"(x));
    return __uint_as_float(u);
}

__device__ __forceinline__ void mma_tf32(float* d, const uint32_t* a, const uint32_t* b) {
    asm volatile(
        "mma.sync.aligned.m16n8k8.row.col.f32.tf32.tf32.f32 "
        "{%0,%1,%2,%3}, {%4,%5,%6,%7}, {%8,%9}, {%0,%1,%2,%3};\n"
        : "+f"(d[0]), "+f"(d[1]), "+f"(d[2]), "+f"(d[3])
        : "r"(a[0]), "r"(a[1]), "r"(a[2]), "r"(a[3]), "r"(b[0]), "r"(b[1]));
}

__device__ __forceinline__ float sigm(float x) { return 1.0f / (1.0f + expf(-x)); }

// One CTA: 256 threads = 8 warps in a 2(M) x 4(N) grid.
// CTA tile: M=32 rows, N=128 cols, K-tile=16.
// For STEP modes, the 128 N-cols are gate-interleaved: col c -> weight row
// (c/32)*512 + ntile*32 + (c%32), so all 4 gates of one 32-wide h-slice live in
// this CTA and the LSTM cell update is applied locally after an SMEM exchange.
template <int MODE, int KTOT>
__global__ __launch_bounds__(256) void k_gemm(
    const float* __restrict__ A0, const float* __restrict__ A1,
    const float* __restrict__ W0, const float* __restrict__ W1,
    const float* __restrict__ bias0, const float* __restrict__ bias1,
    float* __restrict__ outp, float* __restrict__ cbuf, int t)
{
    __shared__ float As[32][20];     // [m][k], padded
    __shared__ float Bs[128][20];    // [n][k], padded
    __shared__ float Cex[32][132];   // gate exchange (STEP modes)

    const int tid  = threadIdx.x;
    const int lane = tid & 31;
    const int w    = tid >> 5;
    const int mw   = w >> 2;     // 0..1
    const int nw   = w & 3;      // 0..3
    const int mtile = blockIdx.y;
    const int ntile = blockIdx.x;

    float acc[4][4];
#pragma unroll
    for (int j = 0; j < 4; j++)
#pragma unroll
        for (int k = 0; k < 4; k++) acc[j][k] = 0.0f;

    // A-load mapping: 32x16 = 512 elems, 2 per thread
    const int a_r  = tid >> 3;
    const int a_kk = (tid & 7) * 2;
    // B-load mapping: 128x16 = 2048 elems, 8 per thread
    const int b_n   = tid >> 1;
    const int b_kk8 = (tid & 1) * 8;

    int b_wrow;
    if (MODE == MODE_PROJ0)      b_wrow = ntile * 128 + b_n;
    else if (MODE == MODE_FC)    b_wrow = b_n;
    else                         b_wrow = (b_n >> 5) * kH + ntile * 32 + (b_n & 31);

#pragma unroll 1
    for (int kt = 0; kt < KTOT; kt += 16) {
        // ---- load A tile ----
        {
            const int gm = mtile * 32 + a_r;
            const int gk = kt + a_kk;
            float2 v;
            if (MODE == MODE_STEP1) {
                const float* src = (gk < kH) ? A0 : A1;
                const int kl = (gk < kH) ? gk : gk - kH;
                v = *(const float2*)&src[gm * kH + kl];
            } else if (MODE == MODE_PROJ0) {
                v = *(const float2*)&A0[(size_t)gm * kI + gk];
            } else {  // STEP0, FC
                v = *(const float2*)&A0[gm * kH + gk];
            }
            As[a_r][a_kk]     = to_tf32(v.x);
            As[a_r][a_kk + 1] = to_tf32(v.y);
        }
        // ---- load B tile (W row-major [rows, K]) ----
        {
            const int gk = kt + b_kk8;
            const float* wsrc;
            int kw, kl = gk;
            if (MODE == MODE_STEP1) {
                if (gk < kH) { wsrc = W0; } else { wsrc = W1; kl = gk - kH; }
                kw = kH;
            } else if (MODE == MODE_PROJ0) {
                wsrc = W0; kw = kI;
            } else {  // STEP0 (W_hh0, K=512), FC (fc_w, K=512)
                wsrc = W0; kw = kH;
            }
            const float4* p = (const float4*)&wsrc[(size_t)b_wrow * kw + kl];
            float4 v0 = p[0], v1 = p[1];
            Bs[b_n][b_kk8 + 0] = to_tf32(v0.x);
            Bs[b_n][b_kk8 + 1] = to_tf32(v0.y);
            Bs[b_n][b_kk8 + 2] = to_tf32(v0.z);
            Bs[b_n][b_kk8 + 3] = to_tf32(v0.w);
            Bs[b_n][b_kk8 + 4] = to_tf32(v1.x);
            Bs[b_n][b_kk8 + 5] = to_tf32(v1.y);
            Bs[b_n][b_kk8 + 6] = to_tf32(v1.z);
            Bs[b_n][b_kk8 + 7] = to_tf32(v1.w);
        }
        __syncthreads();

        // ---- MMA over this k-tile ----
#pragma unroll
        for (int k8 = 0; k8 < 16; k8 += 8) {
            uint32_t a[4];
            const int ar = mw * 16 + (lane >> 2);
            const int ac = k8 + (lane & 3);
            a[0] = __float_as_uint(As[ar][ac]);
            a[1] = __float_as_uint(As[ar + 8][ac]);
            a[2] = __float_as_uint(As[ar][ac + 4]);
            a[3] = __float_as_uint(As[ar + 8][ac + 4]);
#pragma unroll
            for (int j = 0; j < 4; j++) {
                uint32_t b[2];
                const int bn = nw * 32 + j * 8 + (lane >> 2);
                b[0] = __float_as_uint(Bs[bn][k8 + (lane & 3)]);
                b[1] = __float_as_uint(Bs[bn][k8 + (lane & 3) + 4]);
                mma_tf32(acc[j], a, b);
            }
        }
        __syncthreads();
    }

    if (MODE == MODE_PROJ0 || MODE == MODE_FC) {
        const int gr = mtile * 32 + mw * 16 + (lane >> 2);
        const int cbase = (MODE == MODE_PROJ0 ? ntile * 128 : 0) + nw * 32 + (lane & 3) * 2;
        const int ldc = (MODE == MODE_PROJ0) ? kFH : kO;
#pragma unroll
        for (int j = 0; j < 4; j++) {
            const int c0 = cbase + j * 8;
            float bv0, bv1;
            if (MODE == MODE_PROJ0) {
                bv0 = bias0[c0] + bias1[c0];
                bv1 = bias0[c0 + 1] + bias1[c0 + 1];
            } else {
                bv0 = bias0[c0];
                bv1 = bias0[c0 + 1];
            }
            outp[(size_t)gr * ldc + c0]           = acc[j][0] + bv0;
            outp[(size_t)gr * ldc + c0 + 1]       = acc[j][1] + bv1;
            outp[(size_t)(gr + 8) * ldc + c0]     = acc[j][2] + bv0;
            outp[(size_t)(gr + 8) * ldc + c0 + 1] = acc[j][3] + bv1;
        }
    } else {
        // STEP modes: exchange C via SMEM, then apply LSTM cell update.
        const int cr = mw * 16 + (lane >> 2);
        const int cc = nw * 32 + (lane & 3) * 2;
#pragma unroll
        for (int j = 0; j < 4; j++) {
            Cex[cr][cc + j * 8]         = acc[j][0];
            Cex[cr][cc + j * 8 + 1]     = acc[j][1];
            Cex[cr + 8][cc + j * 8]     = acc[j][2];
            Cex[cr + 8][cc + j * 8 + 1] = acc[j][3];
        }
        __syncthreads();

#pragma unroll
        for (int it = 0; it < 4; it++) {
            const int id = tid + it * 256;     // 0..1023 -> 32 rows x 32 h-cols
            const int m  = id >> 5;
            const int hl = id & 31;
            const int gb   = mtile * 32 + m;       // global batch row
            const int hcol = ntile * 32 + hl;      // global h column

            float pi, pf, pg, po;
            if (MODE == MODE_STEP0) {
                const float* xp = &g_xp0[((size_t)gb * kT + t) * kFH];
                pi = Cex[m][hl]      + xp[hcol];
                pf = Cex[m][32 + hl] + xp[kH + hcol];
                pg = Cex[m][64 + hl] + xp[2 * kH + hcol];
                po = Cex[m][96 + hl] + xp[3 * kH + hcol];
            } else {
                pi = Cex[m][hl]      + bias0[hcol]          + bias1[hcol];
                pf = Cex[m][32 + hl] + bias0[kH + hcol]     + bias1[kH + hcol];
                pg = Cex[m][64 + hl] + bias0[2 * kH + hcol] + bias1[2 * kH + hcol];
                po = Cex[m][96 + hl] + bias0[3 * kH + hcol] + bias1[3 * kH + hcol];
            }
            const float ig = sigm(pi);
            const float fg = sigm(pf);
            const float gg = tanhf(pg);
            const float og = sigm(po);
            const int idx = gb * kH + hcol;
            const float cn = fg * cbuf[idx] + ig * gg;
            cbuf[idx] = cn;
            outp[idx] = og * tanhf(cn);
        }
    }
}

extern "C" void kernel_launch(void* const* d_in, const int* in_sizes, int n_in,
                              void* d_out, int out_size)
{
    const float* x     = (const float*)d_in[0];
    const float* W_ih0 = (const float*)d_in[1];
    const float* W_hh0 = (const float*)d_in[2];
    const float* b_ih0 = (const float*)d_in[3];
    const float* b_hh0 = (const float*)d_in[4];
    const float* W_ih1 = (const float*)d_in[5];
    const float* W_hh1 = (const float*)d_in[6];
    const float* b_ih1 = (const float*)d_in[7];
    const float* b_hh1 = (const float*)d_in[8];
    const float* fc_w  = (const float*)d_in[9];
    const float* fc_b  = (const float*)d_in[10];

    float *xp0p, *h1p, *h2p, *c1p, *c2p;
    cudaGetSymbolAddress((void**)&xp0p, g_xp0);
    cudaGetSymbolAddress((void**)&h1p,  g_h1);
    cudaGetSymbolAddress((void**)&h2p,  g_h2);
    cudaGetSymbolAddress((void**)&c1p,  g_c1);
    cudaGetSymbolAddress((void**)&c2p,  g_c2);

    // Reset recurrent state every call (graph replays must be deterministic).
    cudaMemsetAsync(h1p, 0, kBH * sizeof(float), 0);  // h1 buffer [0]
    cudaMemsetAsync(h2p, 0, kBH * sizeof(float), 0);  // h2 buffer [0]
    cudaMemsetAsync(c1p, 0, kBH * sizeof(float), 0);
    cudaMemsetAsync(c2p, 0, kBH * sizeof(float), 0);

    // Layer-0 input projection: xp0[b*T+t, :] = x . W_ih0^T + b_ih0 + b_hh0
    k_gemm<MODE_PROJ0, kI><<<dim3(16, kBT / 32), 256>>>(
        x, nullptr, W_ih0, nullptr, b_ih0, b_hh0, xp0p, nullptr, 0);

    // Fused 2-layer scan: layer-1's input projection folded into its step GEMM.
    for (int t = 0; t < kT; t++) {
        float* h1r = h1p + (t & 1) * kBH;
        float* h1w = h1p + ((t + 1) & 1) * kBH;
        float* h2r = h2p + (t & 1) * kBH;
        float* h2w = h2p + ((t + 1) & 1) * kBH;
        k_gemm<MODE_STEP0, kH><<<dim3(16, 4), 256>>>(
            h1r, nullptr, W_hh0, nullptr, nullptr, nullptr, h1w, c1p, t);
        k_gemm<MODE_STEP1, 2 * kH><<<dim3(16, 4), 256>>>(
            h1w, h2r, W_ih1, W_hh1, b_ih1, b_hh1, h2w, c2p, t);
    }

    // FC head: out = h2[T-1] . fc_w^T + fc_b  (final h2 lands in buffer [0])
    k_gemm<MODE_FC, kH><<<dim3(1, 4), 256>>>(
        h2p, nullptr, fc_w, nullptr, fc_b, nullptr, (float*)d_out, nullptr, 0);
}

// round 2
// speedup vs baseline: 1.0002x; 1.0002x over previous
#include <cuda_runtime.h>
#include <cstdint>
#include <cstddef>

// Problem dims
constexpr int kB  = 128;   // batch
constexpr int kT  = 256;   // timesteps
constexpr int kI  = 256;   // input features
constexpr int kH  = 512;   // hidden
constexpr int kO  = 128;   // output
constexpr int kFH = 4 * kH;           // 2048 (gate rows i,f,g,o)
constexpr int kBH = kB * kH;          // 65536
constexpr int kBT = kB * kT;          // 32768

// Scratch (device-global; no dynamic allocation allowed)
__device__ float g_xp0[(size_t)kBT * kFH];  // layer-0 input projection (+biases), 256 MB
__device__ float g_h1[2][kBH];              // layer-1 hidden, double buffered
__device__ float g_h2[2][kBH];              // layer-2 hidden, double buffered
__device__ float g_c1[kBH];                 // layer-1 cell state
__device__ float g_c2[kBH];                 // layer-2 cell state

enum { MODE_PROJ0 = 0, MODE_STEP0 = 1, MODE_STEP1 = 2, MODE_FC = 3 };

__device__ __forceinline__ float to_tf32(float x) {
    uint32_t u;
    asm("cvt.rna.tf32.f32 %0, %1;" : "=r"(u) : "f"(x));
    return __uint_as_float(u);
}

__device__ __forceinline__ void mma_tf32(float* d, const uint32_t* a, const uint32_t* b) {
    asm volatile(
        "mma.sync.aligned.m16n8k8.row.col.f32.tf32.tf32.f32 "
        "{%0,%1,%2,%3}, {%4,%5,%6,%7}, {%8,%9}, {%0,%1,%2,%3};\n"
        : "+f"(d[0]), "+f"(d[1]), "+f"(d[2]), "+f"(d[3])
        : "r"(a[0]), "r"(a[1]), "r"(a[2]), "r"(a[3]), "r"(b[0]), "r"(b[1]));
}

__device__ __forceinline__ float sigm(float x) { return 1.0f / (1.0f + expf(-x)); }

// One CTA: 256 threads = 8 warps in a 2(M) x 4(N) grid.
// CTA tile: M=32 rows, N=128 cols, K-tile=16.
// For STEP modes, the 128 N-cols are gate-interleaved: col c -> weight row
// (c/32)*512 + ntile*32 + (c%32), so all 4 gates of one 32-wide h-slice live in
// this CTA and the LSTM cell update is applied locally after an SMEM exchange.
template <int MODE, int KTOT>
__global__ __launch_bounds__(256) void k_gemm(
    const float* __restrict__ A0, const float* __restrict__ A1,
    const float* __restrict__ W0, const float* __restrict__ W1,
    const float* __restrict__ bias0, const float* __restrict__ bias1,
    float* __restrict__ outp, float* __restrict__ cbuf, int t)
{
    __shared__ float As[32][20];     // [m][k], padded
    __shared__ float Bs[128][20];    // [n][k], padded
    __shared__ float Cex[32][132];   // gate exchange (STEP modes)

    const int tid  = threadIdx.x;
    const int lane = tid & 31;
    const int w    = tid >> 5;
    const int mw   = w >> 2;     // 0..1
    const int nw   = w & 3;      // 0..3
    const int mtile = blockIdx.y;
    const int ntile = blockIdx.x;

    float acc[4][4];
#pragma unroll
    for (int j = 0; j < 4; j++)
#pragma unroll
        for (int k = 0; k < 4; k++) acc[j][k] = 0.0f;

    // A-load mapping: 32x16 = 512 elems, 2 per thread
    const int a_r  = tid >> 3;
    const int a_kk = (tid & 7) * 2;
    // B-load mapping: 128x16 = 2048 elems, 8 per thread
    const int b_n   = tid >> 1;
    const int b_kk8 = (tid & 1) * 8;

    int b_wrow;
    if (MODE == MODE_PROJ0)      b_wrow = ntile * 128 + b_n;
    else if (MODE == MODE_FC)    b_wrow = b_n;
    else                         b_wrow = (b_n >> 5) * kH + ntile * 32 + (b_n & 31);

#pragma unroll 1
    for (int kt = 0; kt < KTOT; kt += 16) {
        // ---- load A tile ----
        {
            const int gm = mtile * 32 + a_r;
            const int gk = kt + a_kk;
            float2 v;
            if (MODE == MODE_STEP1) {
                const float* src = (gk < kH) ? A0 : A1;
                const int kl = (gk < kH) ? gk : gk - kH;
                v = *(const float2*)&src[gm * kH + kl];
            } else if (MODE == MODE_PROJ0) {
                v = *(const float2*)&A0[(size_t)gm * kI + gk];
            } else {  // STEP0, FC
                v = *(const float2*)&A0[gm * kH + gk];
            }
            As[a_r][a_kk]     = to_tf32(v.x);
            As[a_r][a_kk + 1] = to_tf32(v.y);
        }
        // ---- load B tile (W row-major [rows, K]) ----
        {
            const int gk = kt + b_kk8;
            const float* wsrc;
            int kw, kl = gk;
            if (MODE == MODE_STEP1) {
                if (gk < kH) { wsrc = W0; } else { wsrc = W1; kl = gk - kH; }
                kw = kH;
            } else if (MODE == MODE_PROJ0) {
                wsrc = W0; kw = kI;
            } else {  // STEP0 (W_hh0, K=512), FC (fc_w, K=512)
                wsrc = W0; kw = kH;
            }
            const float4* p = (const float4*)&wsrc[(size_t)b_wrow * kw + kl];
            float4 v0 = p[0], v1 = p[1];
            Bs[b_n][b_kk8 + 0] = to_tf32(v0.x);
            Bs[b_n][b_kk8 + 1] = to_tf32(v0.y);
            Bs[b_n][b_kk8 + 2] = to_tf32(v0.z);
            Bs[b_n][b_kk8 + 3] = to_tf32(v0.w);
            Bs[b_n][b_kk8 + 4] = to_tf32(v1.x);
            Bs[b_n][b_kk8 + 5] = to_tf32(v1.y);
            Bs[b_n][b_kk8 + 6] = to_tf32(v1.z);
            Bs[b_n][b_kk8 + 7] = to_tf32(v1.w);
        }
        __syncthreads();

        // ---- MMA over this k-tile ----
#pragma unroll
        for (int k8 = 0; k8 < 16; k8 += 8) {
            uint32_t a[4];
            const int ar = mw * 16 + (lane >> 2);
            const int ac = k8 + (lane & 3);
            a[0] = __float_as_uint(As[ar][ac]);
            a[1] = __float_as_uint(As[ar + 8][ac]);
            a[2] = __float_as_uint(As[ar][ac + 4]);
            a[3] = __float_as_uint(As[ar + 8][ac + 4]);
#pragma unroll
            for (int j = 0; j < 4; j++) {
                uint32_t b[2];
                const int bn = nw * 32 + j * 8 + (lane >> 2);
                b[0] = __float_as_uint(Bs[bn][k8 + (lane & 3)]);
                b[1] = __float_as_uint(Bs[bn][k8 + (lane & 3) + 4]);
                mma_tf32(acc[j], a, b);
            }
        }
        __syncthreads();
    }

    if (MODE == MODE_PROJ0 || MODE == MODE_FC) {
        const int gr = mtile * 32 + mw * 16 + (lane >> 2);
        const int cbase = (MODE == MODE_PROJ0 ? ntile * 128 : 0) + nw * 32 + (lane & 3) * 2;
        const int ldc = (MODE == MODE_PROJ0) ? kFH : kO;
#pragma unroll
        for (int j = 0; j < 4; j++) {
            const int c0 = cbase + j * 8;
            float bv0, bv1;
            if (MODE == MODE_PROJ0) {
                bv0 = bias0[c0] + bias1[c0];
                bv1 = bias0[c0 + 1] + bias1[c0 + 1];
            } else {
                bv0 = bias0[c0];
                bv1 = bias0[c0 + 1];
            }
            outp[(size_t)gr * ldc + c0]           = acc[j][0] + bv0;
            outp[(size_t)gr * ldc + c0 + 1]       = acc[j][1] + bv1;
            outp[(size_t)(gr + 8) * ldc + c0]     = acc[j][2] + bv0;
            outp[(size_t)(gr + 8) * ldc + c0 + 1] = acc[j][3] + bv1;
        }
    } else {
        // STEP modes: exchange C via SMEM, then apply LSTM cell update.
        const int cr = mw * 16 + (lane >> 2);
        const int cc = nw * 32 + (lane & 3) * 2;
#pragma unroll
        for (int j = 0; j < 4; j++) {
            Cex[cr][cc + j * 8]         = acc[j][0];
            Cex[cr][cc + j * 8 + 1]     = acc[j][1];
            Cex[cr + 8][cc + j * 8]     = acc[j][2];
            Cex[cr + 8][cc + j * 8 + 1] = acc[j][3];
        }
        __syncthreads();

#pragma unroll
        for (int it = 0; it < 4; it++) {
            const int id = tid + it * 256;     // 0..1023 -> 32 rows x 32 h-cols
            const int m  = id >> 5;
            const int hl = id & 31;
            const int gb   = mtile * 32 + m;       // global batch row
            const int hcol = ntile * 32 + hl;      // global h column

            float pi, pf, pg, po;
            if (MODE == MODE_STEP0) {
                const float* xp = &g_xp0[((size_t)gb * kT + t) * kFH];
                pi = Cex[m][hl]      + xp[hcol];
                pf = Cex[m][32 + hl] + xp[kH + hcol];
                pg = Cex[m][64 + hl] + xp[2 * kH + hcol];
                po = Cex[m][96 + hl] + xp[3 * kH + hcol];
            } else {
                pi = Cex[m][hl]      + bias0[hcol]          + bias1[hcol];
                pf = Cex[m][32 + hl] + bias0[kH + hcol]     + bias1[kH + hcol];
                pg = Cex[m][64 + hl] + bias0[2 * kH + hcol] + bias1[2 * kH + hcol];
                po = Cex[m][96 + hl] + bias0[3 * kH + hcol] + bias1[3 * kH + hcol];
            }
            const float ig = sigm(pi);
            const float fg = sigm(pf);
            const float gg = tanhf(pg);
            const float og = sigm(po);
            const int idx = gb * kH + hcol;
            const float cn = fg * cbuf[idx] + ig * gg;
            cbuf[idx] = cn;
            outp[idx] = og * tanhf(cn);
        }
    }
}

extern "C" void kernel_launch(void* const* d_in, const int* in_sizes, int n_in,
                              void* d_out, int out_size)
{
    const float* x     = (const float*)d_in[0];
    const float* W_ih0 = (const float*)d_in[1];
    const float* W_hh0 = (const float*)d_in[2];
    const float* b_ih0 = (const float*)d_in[3];
    const float* b_hh0 = (const float*)d_in[4];
    const float* W_ih1 = (const float*)d_in[5];
    const float* W_hh1 = (const float*)d_in[6];
    const float* b_ih1 = (const float*)d_in[7];
    const float* b_hh1 = (const float*)d_in[8];
    const float* fc_w  = (const float*)d_in[9];
    const float* fc_b  = (const float*)d_in[10];

    float *xp0p, *h1p, *h2p, *c1p, *c2p;
    cudaGetSymbolAddress((void**)&xp0p, g_xp0);
    cudaGetSymbolAddress((void**)&h1p,  g_h1);
    cudaGetSymbolAddress((void**)&h2p,  g_h2);
    cudaGetSymbolAddress((void**)&c1p,  g_c1);
    cudaGetSymbolAddress((void**)&c2p,  g_c2);

    // Reset recurrent state every call (graph replays must be deterministic).
    cudaMemsetAsync(h1p, 0, kBH * sizeof(float), 0);  // h1 buffer [0]
    cudaMemsetAsync(h2p, 0, kBH * sizeof(float), 0);  // h2 buffer [0]
    cudaMemsetAsync(c1p, 0, kBH * sizeof(float), 0);
    cudaMemsetAsync(c2p, 0, kBH * sizeof(float), 0);

    // Layer-0 input projection: xp0[b*T+t, :] = x . W_ih0^T + b_ih0 + b_hh0
    k_gemm<MODE_PROJ0, kI><<<dim3(16, kBT / 32), 256>>>(
        x, nullptr, W_ih0, nullptr, b_ih0, b_hh0, xp0p, nullptr, 0);

    // Fused 2-layer scan: layer-1's input projection folded into its step GEMM.
    for (int t = 0; t < kT; t++) {
        float* h1r = h1p + (t & 1) * kBH;
        float* h1w = h1p + ((t + 1) & 1) * kBH;
        float* h2r = h2p + (t & 1) * kBH;
        float* h2w = h2p + ((t + 1) & 1) * kBH;
        k_gemm<MODE_STEP0, kH><<<dim3(16, 4), 256>>>(
            h1r, nullptr, W_hh0, nullptr, nullptr, nullptr, h1w, c1p, t);
        k_gemm<MODE_STEP1, 2 * kH><<<dim3(16, 4), 256>>>(
            h1w, h2r, W_ih1, W_hh1, b_ih1, b_hh1, h2w, c2p, t);
    }

    // FC head: out = h2[T-1] . fc_w^T + fc_b  (final h2 lands in buffer [0])
    k_gemm<MODE_FC, kH><<<dim3(1, 4), 256>>>(
        h2p, nullptr, fc_w, nullptr, fc_b, nullptr, (float*)d_out, nullptr, 0);
}

// round 3
// speedup vs baseline: 2.7823x; 2.7818x over previous
#include <cuda_runtime.h>
#include <cstdint>
#include <cstddef>

constexpr int kB = 128, kT = 256, kI = 256, kH = 512, kO = 128;
constexpr int kFH = 4 * kH, kBH = kB * kH, kBT = kB * kT;

__device__ float g_xp0[(size_t)kBT * kFH];   // [t][b][4H] layer-0 input proj (+biases)
__device__ float g_h1[2][kBH];
__device__ float g_h2[2][kBH];
__device__ unsigned g_bar[2];                // [0]=arrivals (monotonic), [1]=generation

constexpr int GRID = 128, NTHR = 256;

// SMEM layout (in floats)
constexpr int SM_WH0 = 0;                 // each W slice: 32 cols x 512 k = 16384
constexpr int SM_WI1 = 16384;
constexpr int SM_WH1 = 32768;
constexpr int SM_AS  = 49152;             // A staging: 2 x (64 rows x 68)
constexpr int AS_LD  = 68;
constexpr int AS_BUF = 64 * AS_LD;        // 4352
constexpr int SM_CEX = SM_AS;             // gate exchange aliases A-buf0 (64x33=2112)
constexpr int CEX_LD = 33;
constexpr int SM_B2  = SM_AS + 2 * AS_BUF; // 57856
constexpr int SM_TOTF = SM_B2 + 32;        // 57888 floats = 231552 B
constexpr size_t SMEM_BYTES = (size_t)SM_TOTF * sizeof(float);

__device__ __forceinline__ float to_tf32(float x) {
    uint32_t u;
    asm("cvt.rna.tf32.f32 %0, %1;" : "=r"(u) : "f"(x));
    return __uint_as_float(u);
}

__device__ __forceinline__ void mma_tf32(float* d, const uint32_t* a, const uint32_t* b) {
    asm volatile(
        "mma.sync.aligned.m16n8k8.row.col.f32.tf32.tf32.f32 "
        "{%0,%1,%2,%3}, {%4,%5,%6,%7}, {%8,%9}, {%0,%1,%2,%3};\n"
        : "+f"(d[0]), "+f"(d[1]), "+f"(d[2]), "+f"(d[3])
        : "r"(a[0]), "r"(a[1]), "r"(a[2]), "r"(a[3]), "r"(b[0]), "r"(b[1]));
}

__device__ __forceinline__ float sigm(float x) { return 1.0f / (1.0f + expf(-x)); }

// =====================================================================
// Persistent fused 2-layer LSTM scan. CTA c: mcta=c&1 -> rows [mcta*64,+64),
// ncta=c>>1 -> h-cols [ncta*8,+8) of BOTH layers (32 gate-cols each).
// Iter it: layer-1 step it (it<kT), layer-2 step it-1 (it>=1).
// 8 warps: mw=w>>1 (16-row stripe), nwp=w&1 (16 of 32 gate-cols).
// =====================================================================
__global__ void __launch_bounds__(NTHR, 1) k_scan(
    const float* __restrict__ Whh0, const float* __restrict__ Wih1,
    const float* __restrict__ Whh1, const float* __restrict__ bih1,
    const float* __restrict__ bhh1)
{
    extern __shared__ float sm[];
    const int tid  = threadIdx.x;
    const int lane = tid & 31;
    const int w    = tid >> 5;
    const int mw   = w >> 1;
    const int nwp  = w & 1;
    const int mcta = blockIdx.x & 1;
    const int ncta = blockIdx.x >> 1;
    const int hbase = ncta * 8;
    const int row0  = mcta * 64;

    // ---- Load weight slices, fragment-interleaved ----
    // cc=0..31: gate=cc>>3, hcol=hbase+(cc&7). frag idx for (cc,k):
    // ((k8*4 + tile)*32 + lane)*2 + reg ; tile=cc>>3, lane=((cc&7)<<2)|(k&3), reg=(k>>2)&1
    for (int i = tid; i < 32 * 512; i += NTHR) {
        const int cc = i >> 9, k = i & 511;
        const int grow = (cc >> 3) * kH + hbase + (cc & 7);
        const int idx = (((k >> 3) * 4 + (cc >> 3)) * 32 + (((cc & 7) << 2) | (k & 3))) * 2
                        + ((k >> 2) & 1);
        sm[SM_WH0 + idx] = to_tf32(Whh0[grow * kH + k]);
        sm[SM_WI1 + idx] = to_tf32(Wih1[grow * kH + k]);
        sm[SM_WH1 + idx] = to_tf32(Whh1[grow * kH + k]);
    }
    if (tid < 32) {
        const int grow = (tid >> 3) * kH + hbase + (tid & 7);
        sm[SM_B2 + tid] = bih1[grow] + bhh1[grow];
    }
    __syncthreads();

    const int cr0 = tid >> 3;      // epilogue cell row (plus 32*e)
    const int cj  = tid & 7;       // epilogue h-col
    float c1s[2] = {0.f, 0.f}, c2s[2] = {0.f, 0.f};
    unsigned gen = 0;

    for (int it = 0; it <= kT; ++it) {
        const bool do1 = (it < kT);
        const bool do2 = (it >= 1);
        const float* __restrict__ h1r = g_h1[it & 1];
        const float* __restrict__ h2r = g_h2[it & 1];
        float* __restrict__ h1w = g_h1[(it + 1) & 1];
        float* __restrict__ h2w = g_h2[(it + 1) & 1];

        float acc1[2][4], acc2[2][4];
#pragma unroll
        for (int j = 0; j < 2; ++j)
#pragma unroll
            for (int q = 0; q < 4; ++q) { acc1[j][q] = 0.f; acc2[j][q] = 0.f; }

        // Prefetch xp0 gate pre-activations for layer-1 epilogue
        float px[2][4];
        if (do1) {
#pragma unroll
            for (int e = 0; e < 2; ++e) {
                const int r = cr0 + e * 32;
                const float* xpp = &g_xp0[((size_t)it * kB + row0 + r) * kFH + hbase + cj];
#pragma unroll
                for (int g = 0; g < 4; ++g) px[e][g] = __ldg(xpp + g * kH);
            }
        }

        // ---- chunked A pipeline: global -> regs -> SMEM ----
        float4 st[2][4];
        auto ldchunk = [&](int c, float4* dst) {
            const float* src = (c < 8) ? h1r : h2r;
            const int kb = (c & 7) * 64;
#pragma unroll
            for (int p = 0; p < 4; ++p) {
                const int f = tid + p * 256;
                const int r = f >> 4, kq = f & 15;
                dst[p] = __ldcg((const float4*)&src[(row0 + r) * kH + kb + kq * 4]);
            }
        };
        auto stchunk = [&](int buf, const float4* v) {
            float* As = sm + SM_AS + buf * AS_BUF;
#pragma unroll
            for (int p = 0; p < 4; ++p) {
                const int f = tid + p * 256;
                const int r = f >> 4, kq = f & 15;
                float4 t;
                t.x = to_tf32(v[p].x); t.y = to_tf32(v[p].y);
                t.z = to_tf32(v[p].z); t.w = to_tf32(v[p].w);
                *(float4*)&As[r * AS_LD + kq * 4] = t;
            }
        };

        ldchunk(0, st[0]);
        stchunk(0, st[0]);
        ldchunk(1, st[1]);
        __syncthreads();

#pragma unroll 1
        for (int c = 0; c < 16; ++c) {
            const float* As = sm + SM_AS + (c & 1) * AS_BUF;
#pragma unroll
            for (int q = 0; q < 8; ++q) {
                const int ar = mw * 16 + (lane >> 2);
                const int ac = q * 8 + (lane & 3);
                uint32_t au[4];
                au[0] = __float_as_uint(As[ar * AS_LD + ac]);
                au[1] = __float_as_uint(As[(ar + 8) * AS_LD + ac]);
                au[2] = __float_as_uint(As[ar * AS_LD + ac + 4]);
                au[3] = __float_as_uint(As[(ar + 8) * AS_LD + ac + 4]);
                if (c < 8) {
                    const int k8g = c * 8 + q;
                    if (do1) {
#pragma unroll
                        for (int j = 0; j < 2; ++j) {
                            const float2 b = *(const float2*)&sm[SM_WH0 +
                                ((k8g * 4 + nwp * 2 + j) * 32 + lane) * 2];
                            uint32_t bu[2] = { __float_as_uint(b.x), __float_as_uint(b.y) };
                            mma_tf32(acc1[j], au, bu);
                        }
                    }
                    if (do2) {
#pragma unroll
                        for (int j = 0; j < 2; ++j) {
                            const float2 b = *(const float2*)&sm[SM_WI1 +
                                ((k8g * 4 + nwp * 2 + j) * 32 + lane) * 2];
                            uint32_t bu[2] = { __float_as_uint(b.x), __float_as_uint(b.y) };
                            mma_tf32(acc2[j], au, bu);
                        }
                    }
                } else if (do2) {
                    const int k8g = (c - 8) * 8 + q;
#pragma unroll
                    for (int j = 0; j < 2; ++j) {
                        const float2 b = *(const float2*)&sm[SM_WH1 +
                            ((k8g * 4 + nwp * 2 + j) * 32 + lane) * 2];
                        uint32_t bu[2] = { __float_as_uint(b.x), __float_as_uint(b.y) };
                        mma_tf32(acc2[j], au, bu);
                    }
                }
            }
            if (c + 1 < 16) stchunk((c + 1) & 1, st[(c + 1) & 1]);
            if (c + 2 < 16) ldchunk(c + 2, st[c & 1]);
            __syncthreads();
        }

        // ---- Layer-1 epilogue ----
        if (do1) {
            {
                const int r    = mw * 16 + (lane >> 2);
                const int colb = nwp * 16 + (lane & 3) * 2;
                float* cx = sm + SM_CEX;
#pragma unroll
                for (int j = 0; j < 2; ++j) {
                    cx[r * CEX_LD + colb + j * 8]           = acc1[j][0];
                    cx[r * CEX_LD + colb + j * 8 + 1]       = acc1[j][1];
                    cx[(r + 8) * CEX_LD + colb + j * 8]     = acc1[j][2];
                    cx[(r + 8) * CEX_LD + colb + j * 8 + 1] = acc1[j][3];
                }
            }
            __syncthreads();
#pragma unroll
            for (int e = 0; e < 2; ++e) {
                const int r = cr0 + e * 32;
                const float* cx = sm + SM_CEX + r * CEX_LD;
                const float ig = sigm(cx[cj]      + px[e][0]);
                const float fg = sigm(cx[8 + cj]  + px[e][1]);
                const float gg = tanhf(cx[16 + cj] + px[e][2]);
                const float og = sigm(cx[24 + cj] + px[e][3]);
                const float cn = fg * c1s[e] + ig * gg;
                c1s[e] = cn;
                h1w[(row0 + r) * kH + hbase + cj] = og * tanhf(cn);
            }
            __syncthreads();
        }

        // ---- Layer-2 epilogue ----
        if (do2) {
            {
                const int r    = mw * 16 + (lane >> 2);
                const int colb = nwp * 16 + (lane & 3) * 2;
                float* cx = sm + SM_CEX;
#pragma unroll
                for (int j = 0; j < 2; ++j) {
                    cx[r * CEX_LD + colb + j * 8]           = acc2[j][0];
                    cx[r * CEX_LD + colb + j * 8 + 1]       = acc2[j][1];
                    cx[(r + 8) * CEX_LD + colb + j * 8]     = acc2[j][2];
                    cx[(r + 8) * CEX_LD + colb + j * 8 + 1] = acc2[j][3];
                }
            }
            __syncthreads();
#pragma unroll
            for (int e = 0; e < 2; ++e) {
                const int r = cr0 + e * 32;
                const float* cx = sm + SM_CEX + r * CEX_LD;
                const float ig = sigm(cx[cj]      + sm[SM_B2 + cj]);
                const float fg = sigm(cx[8 + cj]  + sm[SM_B2 + 8 + cj]);
                const float gg = tanhf(cx[16 + cj] + sm[SM_B2 + 16 + cj]);
                const float og = sigm(cx[24 + cj] + sm[SM_B2 + 24 + cj]);
                const float cn = fg * c2s[e] + ig * gg;
                c2s[e] = cn;
                h2w[(row0 + r) * kH + hbase + cj] = og * tanhf(cn);
            }
        }

        // ---- Grid barrier (all 128 CTAs resident; counters memset per call) ----
        __threadfence();
        __syncthreads();
        if (tid == 0) {
            unsigned a;
            asm volatile("atom.release.gpu.add.u32 %0, [%1], %2;"
                         : "=r"(a) : "l"(&g_bar[0]), "r"(1u) : "memory");
            const unsigned tgt = (gen + 1) * GRID;
            if (a == tgt - 1) {
                asm volatile("st.release.gpu.u32 [%0], %1;"
                             :: "l"(&g_bar[1]), "r"(gen + 1) : "memory");
            } else {
                unsigned v;
                do {
                    asm volatile("ld.acquire.gpu.u32 %0, [%1];"
                                 : "=r"(v) : "l"(&g_bar[1]) : "memory");
                    if (v > gen) break;
                    __nanosleep(32);
                } while (true);
            }
        }
        ++gen;
        __syncthreads();
    }
}

// =====================================================================
// MODE 0: layer-0 input projection (out transposed to [t][b][4H]).
// MODE 1: FC head.
// =====================================================================
template <int MODE, int KTOT>
__global__ __launch_bounds__(256) void k_io(
    const float* __restrict__ A0, const float* __restrict__ W0,
    const float* __restrict__ bias0, const float* __restrict__ bias1,
    float* __restrict__ outp)
{
    __shared__ float As[32][20];
    __shared__ float Bs[128][20];

    const int tid  = threadIdx.x;
    const int lane = tid & 31;
    const int w    = tid >> 5;
    const int mw   = w >> 2;
    const int nw   = w & 3;
    const int mtile = blockIdx.y;
    const int ntile = blockIdx.x;

    float acc[4][4];
#pragma unroll
    for (int j = 0; j < 4; j++)
#pragma unroll
        for (int k = 0; k < 4; k++) acc[j][k] = 0.0f;

    const int a_r  = tid >> 3;
    const int a_kk = (tid & 7) * 2;
    const int b_n   = tid >> 1;
    const int b_kk8 = (tid & 1) * 8;
    const int b_wrow = (MODE == 0) ? (ntile * 128 + b_n) : b_n;
    const int kw = (MODE == 0) ? kI : kH;

#pragma unroll 1
    for (int kt = 0; kt < KTOT; kt += 16) {
        {
            const int gm = mtile * 32 + a_r;
            const float2 v = *(const float2*)&A0[(size_t)gm * kw + kt + a_kk];
            As[a_r][a_kk]     = to_tf32(v.x);
            As[a_r][a_kk + 1] = to_tf32(v.y);
        }
        {
            const float4* p = (const float4*)&W0[(size_t)b_wrow * kw + kt + b_kk8];
            const float4 v0 = p[0], v1 = p[1];
            Bs[b_n][b_kk8 + 0] = to_tf32(v0.x);
            Bs[b_n][b_kk8 + 1] = to_tf32(v0.y);
            Bs[b_n][b_kk8 + 2] = to_tf32(v0.z);
            Bs[b_n][b_kk8 + 3] = to_tf32(v0.w);
            Bs[b_n][b_kk8 + 4] = to_tf32(v1.x);
            Bs[b_n][b_kk8 + 5] = to_tf32(v1.y);
            Bs[b_n][b_kk8 + 6] = to_tf32(v1.z);
            Bs[b_n][b_kk8 + 7] = to_tf32(v1.w);
        }
        __syncthreads();

#pragma unroll
        for (int k8 = 0; k8 < 16; k8 += 8) {
            uint32_t a[4];
            const int ar = mw * 16 + (lane >> 2);
            const int ac = k8 + (lane & 3);
            a[0] = __float_as_uint(As[ar][ac]);
            a[1] = __float_as_uint(As[ar + 8][ac]);
            a[2] = __float_as_uint(As[ar][ac + 4]);
            a[3] = __float_as_uint(As[ar + 8][ac + 4]);
#pragma unroll
            for (int j = 0; j < 4; j++) {
                uint32_t b[2];
                const int bn = nw * 32 + j * 8 + (lane >> 2);
                b[0] = __float_as_uint(Bs[bn][k8 + (lane & 3)]);
                b[1] = __float_as_uint(Bs[bn][k8 + (lane & 3) + 4]);
                mma_tf32(acc[j], a, b);
            }
        }
        __syncthreads();
    }

    const int gr = mtile * 32 + mw * 16 + (lane >> 2);
    const int cbase = (MODE == 0 ? ntile * 128 : 0) + nw * 32 + (lane & 3) * 2;
    // MODE 0 writes transposed rows [t*kB + b]; MODE 1 plain.
    const size_t or0 = (MODE == 0)
        ? ((size_t)((gr & 255) * kB + (gr >> 8))) * kFH
        : (size_t)gr * kO;
    const size_t or1 = (MODE == 0)
        ? ((size_t)(((gr + 8) & 255) * kB + ((gr + 8) >> 8))) * kFH
        : (size_t)(gr + 8) * kO;
#pragma unroll
    for (int j = 0; j < 4; j++) {
        const int c0 = cbase + j * 8;
        float bv0, bv1;
        if (MODE == 0) {
            bv0 = bias0[c0] + bias1[c0];
            bv1 = bias0[c0 + 1] + bias1[c0 + 1];
        } else {
            bv0 = bias0[c0];
            bv1 = bias0[c0 + 1];
        }
        outp[or0 + c0]     = acc[j][0] + bv0;
        outp[or0 + c0 + 1] = acc[j][1] + bv1;
        outp[or1 + c0]     = acc[j][2] + bv0;
        outp[or1 + c0 + 1] = acc[j][3] + bv1;
    }
}

extern "C" void kernel_launch(void* const* d_in, const int* in_sizes, int n_in,
                              void* d_out, int out_size)
{
    const float* x     = (const float*)d_in[0];
    const float* W_ih0 = (const float*)d_in[1];
    const float* W_hh0 = (const float*)d_in[2];
    const float* b_ih0 = (const float*)d_in[3];
    const float* b_hh0 = (const float*)d_in[4];
    const float* W_ih1 = (const float*)d_in[5];
    const float* W_hh1 = (const float*)d_in[6];
    const float* b_ih1 = (const float*)d_in[7];
    const float* b_hh1 = (const float*)d_in[8];
    const float* fc_w  = (const float*)d_in[9];
    const float* fc_b  = (const float*)d_in[10];

    float *xp0p, *h1p, *h2p;
    unsigned* barp;
    cudaGetSymbolAddress((void**)&xp0p, g_xp0);
    cudaGetSymbolAddress((void**)&h1p,  g_h1);
    cudaGetSymbolAddress((void**)&h2p,  g_h2);
    cudaGetSymbolAddress((void**)&barp, g_bar);

    static bool attr_set = false;
    if (!attr_set) {
        cudaFuncSetAttribute(k_scan, cudaFuncAttributeMaxDynamicSharedMemorySize,
                             (int)SMEM_BYTES);
        attr_set = true;
    }

    // Deterministic per-call init (graph-capturable memsets)
    cudaMemsetAsync(h1p, 0, 2 * kBH * sizeof(float), 0);
    cudaMemsetAsync(h2p, 0, 2 * kBH * sizeof(float), 0);
    cudaMemsetAsync(barp, 0, 2 * sizeof(unsigned), 0);

    // Layer-0 input projection -> g_xp0 in [t][b][4H]
    k_io<0, kI><<<dim3(16, kBT / 32), 256>>>(x, W_ih0, b_ih0, b_hh0, xp0p);

    // Persistent fused 2-layer scan
    k_scan<<<GRID, NTHR, SMEM_BYTES>>>(W_hh0, W_ih1, W_hh1, b_ih1, b_hh1);

    // FC head on final h2 (step 255 lands in g_h2[1])
    k_io<1, kH><<<dim3(1, 4), 256>>>(h2p + kBH, fc_w, fc_b, nullptr, (float*)d_out);
}

// round 4
// speedup vs baseline: 3.7276x; 1.3397x over previous
#include <cuda_runtime.h>
#include <cstdint>
#include <cstddef>

constexpr int kB = 128, kT = 256, kI = 256, kH = 512, kO = 128;
constexpr int kFH = 4 * kH, kBH = kB * kH, kBT = kB * kT;

__device__ float g_xp0[(size_t)kBT * kFH];   // [t][b][4H] layer-0 input proj (+biases)
__device__ float g_h1[2][kBH];
__device__ float g_h2[2][kBH];
__device__ unsigned g_bar[2];                // [0]=arrivals (monotonic), [1]=generation

constexpr int GRID = 128, NTHR = 512;

// SMEM layout (floats)
constexpr int SM_WH0 = 0;                  // 32 cols x 512 k, frag-interleaved
constexpr int SM_WI1 = 16384;
constexpr int SM_WH1 = 32768;
constexpr int SM_AS  = 49152;              // A staging: 2 x (64 rows x AS_LD)
constexpr int AS_LD  = 68;                 // 272B rows: 16B-aligned, conflict-free gather
constexpr int AS_BUF = 64 * AS_LD;         // 4352
constexpr int SM_CEX = SM_AS;              // k-split partials [4][64][33] alias A bufs (8448 fl)
constexpr int SM_B2  = SM_AS + 2 * AS_BUF; // 57856
constexpr int SM_TOTF = SM_B2 + 32;        // 57888 floats = 231552 B
constexpr size_t SMEM_BYTES = (size_t)SM_TOTF * sizeof(float);

__device__ __forceinline__ float to_tf32(float x) {
    uint32_t u;
    asm("cvt.rna.tf32.f32 %0, %1;" : "=r"(u) : "f"(x));
    return __uint_as_float(u);
}

__device__ __forceinline__ void mma_tf32(float* d, const uint32_t* a, const uint32_t* b) {
    asm volatile(
        "mma.sync.aligned.m16n8k8.row.col.f32.tf32.tf32.f32 "
        "{%0,%1,%2,%3}, {%4,%5,%6,%7}, {%8,%9}, {%0,%1,%2,%3};\n"
        : "+f"(d[0]), "+f"(d[1]), "+f"(d[2]), "+f"(d[3])
        : "r"(a[0]), "r"(a[1]), "r"(a[2]), "r"(a[3]), "r"(b[0]), "r"(b[1]));
}

__device__ __forceinline__ float sigm(float x) { return 1.0f / (1.0f + expf(-x)); }

// =====================================================================
// Persistent fused 2-layer LSTM scan.
// CTA c: mcta=c&1 -> rows [mcta*64,+64); ncta=c>>1 -> h-cols [ncta*8,+8) of both
// layers (32 gate-cols each). Iter it: layer-1 step it (it<kT), layer-2 step
// it-1 (it>=1). 16 warps: kq=w&3 (k-quarter within each chunk), mw=(w>>2)&1
// (32-row half), nw=(w>>3)&1 (16-col half). Warp tile m32 x n16, 4 mma/k8.
// A (h-activations, pre-rounded to tf32 at store) staged via cp.async.cg in
// 16 chunks of 64 k, double-buffered. k-split partials reduced via SMEM.
// =====================================================================
__global__ void __launch_bounds__(NTHR, 1) k_scan(
    const float* __restrict__ Whh0, const float* __restrict__ Wih1,
    const float* __restrict__ Whh1, const float* __restrict__ bih1,
    const float* __restrict__ bhh1)
{
    extern __shared__ float sm[];
    const int tid  = threadIdx.x;
    const int lane = tid & 31;
    const int w    = tid >> 5;
    const int kq   = w & 3;
    const int mw   = (w >> 2) & 1;
    const int nw   = (w >> 3) & 1;
    const int mcta = blockIdx.x & 1;
    const int ncta = blockIdx.x >> 1;
    const int hbase = ncta * 8;
    const int row0  = mcta * 64;

    // ---- Weight slices, fragment-interleaved (verified layout from R3) ----
    for (int i = tid; i < 32 * 512; i += NTHR) {
        const int cc = i >> 9, k = i & 511;
        const int grow = (cc >> 3) * kH + hbase + (cc & 7);
        const int idx = (((k >> 3) * 4 + (cc >> 3)) * 32 + (((cc & 7) << 2) | (k & 3))) * 2
                        + ((k >> 2) & 1);
        sm[SM_WH0 + idx] = to_tf32(Whh0[grow * kH + k]);
        sm[SM_WI1 + idx] = to_tf32(Wih1[grow * kH + k]);
        sm[SM_WH1 + idx] = to_tf32(Whh1[grow * kH + k]);
    }
    if (tid < 32) {
        const int grow = (tid >> 3) * kH + hbase + (tid & 7);
        sm[SM_B2 + tid] = bih1[grow] + bhh1[grow];
    }
    __syncthreads();

    const int er = tid >> 3;     // epilogue cell row (0..63)
    const int ej = tid & 7;      // epilogue h-col (0..7)
    float c1s = 0.f, c2s = 0.f;
    unsigned gen = 0;

    for (int it = 0; it <= kT; ++it) {
        const bool do1 = (it < kT);
        const bool do2 = (it >= 1);
        const float* __restrict__ h1r = g_h1[it & 1];
        const float* __restrict__ h2r = g_h2[it & 1];
        float* __restrict__ h1w = g_h1[(it + 1) & 1];
        float* __restrict__ h2w = g_h2[(it + 1) & 1];

        float acc1[2][2][4], acc2[2][2][4];
#pragma unroll
        for (int mi = 0; mi < 2; ++mi)
#pragma unroll
            for (int ni = 0; ni < 2; ++ni)
#pragma unroll
                for (int q = 0; q < 4; ++q) { acc1[mi][ni][q] = 0.f; acc2[mi][ni][q] = 0.f; }

        // xp0 prefetch (consumed by layer-1 epilogue; hides DRAM latency)
        float px[4];
        if (do1) {
            const float* xpp = &g_xp0[((size_t)it * kB + row0 + er) * kFH + hbase + ej];
            px[0] = __ldg(xpp);
            px[1] = __ldg(xpp + kH);
            px[2] = __ldg(xpp + 2 * kH);
            px[3] = __ldg(xpp + 3 * kH);
        }

        // cp.async chunk issue: chunk c<8 -> h1 k[c*64..), c>=8 -> h2
        auto issue_chunk = [&](int c) {
            const float* src = (c < 8) ? h1r : h2r;
            const int kb = (c & 7) * 64;
            float* As = sm + SM_AS + (c & 1) * AS_BUF;
#pragma unroll
            for (int p = 0; p < 2; ++p) {
                const int f = tid + p * NTHR;
                const int r = f >> 4, k4 = f & 15;
                uint32_t dst = (uint32_t)__cvta_generic_to_shared(&As[r * AS_LD + k4 * 4]);
                const float* gp = &src[(row0 + r) * kH + kb + k4 * 4];
                asm volatile("cp.async.cg.shared.global [%0], [%1], 16;"
                             :: "r"(dst), "l"(gp));
            }
            asm volatile("cp.async.commit_group;" ::: "memory");
        };

        issue_chunk(0);
        issue_chunk(1);

#pragma unroll 1
        for (int c = 0; c < 16; ++c) {
            if (c == 15) asm volatile("cp.async.wait_group 0;" ::: "memory");
            else         asm volatile("cp.async.wait_group 1;" ::: "memory");
            __syncthreads();
            const float* As = sm + SM_AS + (c & 1) * AS_BUF;
            const bool ph1 = (c < 8);
#pragma unroll
            for (int kl = 0; kl < 2; ++kl) {
                const int k8l = kq * 2 + kl;               // k8 within chunk (0..7)
                const int k8g = (c & 7) * 8 + k8l;         // k8 within layer K (0..63)
                uint32_t au[2][4];
#pragma unroll
                for (int mi = 0; mi < 2; ++mi) {
                    const int r  = mw * 32 + mi * 16 + (lane >> 2);
                    const int ck = k8l * 8 + (lane & 3);
                    au[mi][0] = __float_as_uint(As[r * AS_LD + ck]);
                    au[mi][1] = __float_as_uint(As[(r + 8) * AS_LD + ck]);
                    au[mi][2] = __float_as_uint(As[r * AS_LD + ck + 4]);
                    au[mi][3] = __float_as_uint(As[(r + 8) * AS_LD + ck + 4]);
                }
                if (ph1) {
#pragma unroll
                    for (int ni = 0; ni < 2; ++ni) {
                        const int tile = nw * 2 + ni;
                        if (do1) {
                            const float2 b = *(const float2*)&sm[SM_WH0 +
                                ((k8g * 4 + tile) * 32 + lane) * 2];
                            uint32_t bu[2] = { __float_as_uint(b.x), __float_as_uint(b.y) };
                            mma_tf32(acc1[0][ni], au[0], bu);
                            mma_tf32(acc1[1][ni], au[1], bu);
                        }
                        if (do2) {
                            const float2 b = *(const float2*)&sm[SM_WI1 +
                                ((k8g * 4 + tile) * 32 + lane) * 2];
                            uint32_t bu[2] = { __float_as_uint(b.x), __float_as_uint(b.y) };
                            mma_tf32(acc2[0][ni], au[0], bu);
                            mma_tf32(acc2[1][ni], au[1], bu);
                        }
                    }
                } else if (do2) {
#pragma unroll
                    for (int ni = 0; ni < 2; ++ni) {
                        const int tile = nw * 2 + ni;
                        const float2 b = *(const float2*)&sm[SM_WH1 +
                            ((k8g * 4 + tile) * 32 + lane) * 2];
                        uint32_t bu[2] = { __float_as_uint(b.x), __float_as_uint(b.y) };
                        mma_tf32(acc2[0][ni], au[0], bu);
                        mma_tf32(acc2[1][ni], au[1], bu);
                    }
                }
            }
            __syncthreads();
            if (c + 2 < 16) issue_chunk(c + 2);
        }

        // ---- Layer-1 epilogue: k-split reduce + cell update ----
        if (do1) {
#pragma unroll
            for (int mi = 0; mi < 2; ++mi)
#pragma unroll
                for (int ni = 0; ni < 2; ++ni) {
                    const int r  = mw * 32 + mi * 16 + (lane >> 2);
                    const int c0 = nw * 16 + ni * 8 + (lane & 3) * 2;
                    float* cx = &sm[SM_CEX + (kq * 64 + r) * 33 + c0];
                    cx[0]          = acc1[mi][ni][0];
                    cx[1]          = acc1[mi][ni][1];
                    cx[8 * 33]     = acc1[mi][ni][2];
                    cx[8 * 33 + 1] = acc1[mi][ni][3];
                }
            __syncthreads();
            {
                float pre[4];
#pragma unroll
                for (int g = 0; g < 4; ++g) {
                    float s = px[g];
#pragma unroll
                    for (int q = 0; q < 4; ++q)
                        s += sm[SM_CEX + (q * 64 + er) * 33 + g * 8 + ej];
                    pre[g] = s;
                }
                const float ig = sigm(pre[0]), fg = sigm(pre[1]);
                const float gg = tanhf(pre[2]), og = sigm(pre[3]);
                const float cn = fg * c1s + ig * gg;
                c1s = cn;
                h1w[(row0 + er) * kH + hbase + ej] = to_tf32(og * tanhf(cn));
            }
            __syncthreads();
        }

        // ---- Layer-2 epilogue ----
        if (do2) {
#pragma unroll
            for (int mi = 0; mi < 2; ++mi)
#pragma unroll
                for (int ni = 0; ni < 2; ++ni) {
                    const int r  = mw * 32 + mi * 16 + (lane >> 2);
                    const int c0 = nw * 16 + ni * 8 + (lane & 3) * 2;
                    float* cx = &sm[SM_CEX + (kq * 64 + r) * 33 + c0];
                    cx[0]          = acc2[mi][ni][0];
                    cx[1]          = acc2[mi][ni][1];
                    cx[8 * 33]     = acc2[mi][ni][2];
                    cx[8 * 33 + 1] = acc2[mi][ni][3];
                }
            __syncthreads();
            {
                float pre[4];
#pragma unroll
                for (int g = 0; g < 4; ++g) {
                    float s = sm[SM_B2 + g * 8 + ej];
#pragma unroll
                    for (int q = 0; q < 4; ++q)
                        s += sm[SM_CEX + (q * 64 + er) * 33 + g * 8 + ej];
                    pre[g] = s;
                }
                const float ig = sigm(pre[0]), fg = sigm(pre[1]);
                const float gg = tanhf(pre[2]), og = sigm(pre[3]);
                const float cn = fg * c2s + ig * gg;
                c2s = cn;
                h2w[(row0 + er) * kH + hbase + ej] = to_tf32(og * tanhf(cn));
            }
        }

        // ---- Grid barrier (all 128 CTAs resident; counters memset per call) ----
        __threadfence();
        __syncthreads();
        if (tid == 0) {
            unsigned a;
            asm volatile("atom.release.gpu.add.u32 %0, [%1], %2;"
                         : "=r"(a) : "l"(&g_bar[0]), "r"(1u) : "memory");
            const unsigned tgt = (gen + 1) * GRID;
            if (a == tgt - 1) {
                asm volatile("st.release.gpu.u32 [%0], %1;"
                             :: "l"(&g_bar[1]), "r"(gen + 1) : "memory");
            } else {
                unsigned v;
                do {
                    asm volatile("ld.acquire.gpu.u32 %0, [%1];"
                                 : "=r"(v) : "l"(&g_bar[1]) : "memory");
                    if (v > gen) break;
                    __nanosleep(32);
                } while (true);
            }
        }
        ++gen;
        __syncthreads();
    }
}

// =====================================================================
// MODE 0: layer-0 input projection (out transposed to [t][b][4H]).
// MODE 1: FC head. Fragment-interleaved SMEM: a-frag = 1 LDS.128,
// b-frag = 1 LDS.64. Tile M=32 x N=128, ktile=16; 8 warps (2M x 4N).
// =====================================================================
template <int MODE, int KTOT>
__global__ __launch_bounds__(256) void k_io(
    const float* __restrict__ A0, const float* __restrict__ W0,
    const float* __restrict__ bias0, const float* __restrict__ bias1,
    float* __restrict__ outp)
{
    __shared__ float Asf[512];    // [(k8*2+mt)*32+lane] float4 = (a0,a1,a2,a3)
    __shared__ float Bsf[2048];   // [(k8*16+tile)*32+lane] float2 = (b0,b1)

    const int tid  = threadIdx.x;
    const int lane = tid & 31;
    const int w    = tid >> 5;
    const int mw   = w >> 2;
    const int nw   = w & 3;
    const int mtile = blockIdx.y;
    const int ntile = blockIdx.x;

    float acc[4][4];
#pragma unroll
    for (int j = 0; j < 4; j++)
#pragma unroll
        for (int q = 0; q < 4; q++) acc[j][q] = 0.0f;

    const int a_r  = tid >> 3;
    const int a_kk = (tid & 7) * 2;
    const int b_n   = tid >> 1;
    const int b_kk8 = (tid & 1) * 8;
    const int b_wrow = (MODE == 0) ? (ntile * 128 + b_n) : b_n;
    const int kw = (MODE == 0) ? kI : kH;

#pragma unroll 1
    for (int kt = 0; kt < KTOT; kt += 16) {
        {
            const int gm = mtile * 32 + a_r;
            const float2 v = *(const float2*)&A0[(size_t)gm * kw + kt + a_kk];
            const float vv[2] = { v.x, v.y };
#pragma unroll
            for (int e = 0; e < 2; ++e) {
                const int k = a_kk + e;
                const int g = (k >> 3) * 2 + (a_r >> 4);
                const int ln = ((a_r & 7) << 2) | (k & 3);
                const int comp = ((a_r >> 3) & 1) | (((k >> 2) & 1) << 1);
                Asf[(g * 32 + ln) * 4 + comp] = to_tf32(vv[e]);
            }
        }
        {
            const float4* p = (const float4*)&W0[(size_t)b_wrow * kw + kt + b_kk8];
            const float4 v0 = p[0], v1 = p[1];
            const float vv[8] = { v0.x, v0.y, v0.z, v0.w, v1.x, v1.y, v1.z, v1.w };
#pragma unroll
            for (int e = 0; e < 8; ++e) {
                const int k = b_kk8 + e;
                const int g = (k >> 3) * 16 + (b_n >> 3);
                const int ln = ((b_n & 7) << 2) | (k & 3);
                const int comp = (k >> 2) & 1;
                Bsf[(g * 32 + ln) * 2 + comp] = to_tf32(vv[e]);
            }
        }
        __syncthreads();

#pragma unroll
        for (int k8 = 0; k8 < 2; ++k8) {
            const float4 af = *(const float4*)&Asf[((k8 * 2 + mw) * 32 + lane) * 4];
            uint32_t au[4] = { __float_as_uint(af.x), __float_as_uint(af.y),
                               __float_as_uint(af.z), __float_as_uint(af.w) };
#pragma unroll
            for (int j = 0; j < 4; ++j) {
                const float2 b = *(const float2*)&Bsf[((k8 * 16 + nw * 4 + j) * 32 + lane) * 2];
                uint32_t bu[2] = { __float_as_uint(b.x), __float_as_uint(b.y) };
                mma_tf32(acc[j], au, bu);
            }
        }
        __syncthreads();
    }

    const int gr = mtile * 32 + mw * 16 + (lane >> 2);
    const int cbase = (MODE == 0 ? ntile * 128 : 0) + nw * 32 + (lane & 3) * 2;
    const size_t or0 = (MODE == 0)
        ? ((size_t)((gr & 255) * kB + (gr >> 8))) * kFH
        : (size_t)gr * kO;
    const size_t or1 = (MODE == 0)
        ? ((size_t)(((gr + 8) & 255) * kB + ((gr + 8) >> 8))) * kFH
        : (size_t)(gr + 8) * kO;
#pragma unroll
    for (int j = 0; j < 4; j++) {
        const int c0 = cbase + j * 8;
        float bv0, bv1;
        if (MODE == 0) {
            bv0 = bias0[c0] + bias1[c0];
            bv1 = bias0[c0 + 1] + bias1[c0 + 1];
        } else {
            bv0 = bias0[c0];
            bv1 = bias0[c0 + 1];
        }
        outp[or0 + c0]     = acc[j][0] + bv0;
        outp[or0 + c0 + 1] = acc[j][1] + bv1;
        outp[or1 + c0]     = acc[j][2] + bv0;
        outp[or1 + c0 + 1] = acc[j][3] + bv1;
    }
}

extern "C" void kernel_launch(void* const* d_in, const int* in_sizes, int n_in,
                              void* d_out, int out_size)
{
    const float* x     = (const float*)d_in[0];
    const float* W_ih0 = (const float*)d_in[1];
    const float* W_hh0 = (const float*)d_in[2];
    const float* b_ih0 = (const float*)d_in[3];
    const float* b_hh0 = (const float*)d_in[4];
    const float* W_ih1 = (const float*)d_in[5];
    const float* W_hh1 = (const float*)d_in[6];
    const float* b_ih1 = (const float*)d_in[7];
    const float* b_hh1 = (const float*)d_in[8];
    const float* fc_w  = (const float*)d_in[9];
    const float* fc_b  = (const float*)d_in[10];

    float *xp0p, *h1p, *h2p;
    unsigned* barp;
    cudaGetSymbolAddress((void**)&xp0p, g_xp0);
    cudaGetSymbolAddress((void**)&h1p,  g_h1);
    cudaGetSymbolAddress((void**)&h2p,  g_h2);
    cudaGetSymbolAddress((void**)&barp, g_bar);

    static bool attr_set = false;
    if (!attr_set) {
        cudaFuncSetAttribute(k_scan, cudaFuncAttributeMaxDynamicSharedMemorySize,
                             (int)SMEM_BYTES);
        attr_set = true;
    }

    // Deterministic per-call init
    cudaMemsetAsync(h1p, 0, 2 * kBH * sizeof(float), 0);
    cudaMemsetAsync(h2p, 0, 2 * kBH * sizeof(float), 0);
    cudaMemsetAsync(barp, 0, 2 * sizeof(unsigned), 0);

    // Layer-0 input projection -> g_xp0 [t][b][4H]
    k_io<0, kI><<<dim3(16, kBT / 32), 256>>>(x, W_ih0, b_ih0, b_hh0, xp0p);

    // Persistent fused 2-layer scan
    k_scan<<<GRID, NTHR, SMEM_BYTES>>>(W_hh0, W_ih1, W_hh1, b_ih1, b_hh1);

    // FC head on final h2 (lands in g_h2[1])
    k_io<1, kH><<<dim3(1, 4), 256>>>(h2p + kBH, fc_w, fc_b, nullptr, (float*)d_out);
}